// round 6
// baseline (speedup 1.0000x reference)
#include <cuda_runtime.h>
#include <cuda_bf16.h>
#include <cstdint>

// Problem constants
#define NN 8192
#define DD 256
#define FF 64
#define SPLITS 4
#define KEYS_PER_SPLIT (NN / SPLITS)   // 2048
#define BK 64
#define TILES_PER_SPLIT (KEYS_PER_SPLIT / BK) // 32
#define NF (NN * FF)

// Scratch (device globals; no allocation allowed)
__device__ float g_k[NN * FF];
__device__ float g_v[NN * FF];
__device__ float g_q[NN * FF];
__device__ float g_op[SPLITS * NN * FF];   // partial numerators
__device__ float g_rs[SPLITS * NN];        // partial exp-sums

// ---------------------------------------------------------------------------
// helpers
// ---------------------------------------------------------------------------
__device__ __forceinline__ unsigned cvt_tf32(float x) {
    unsigned u;
    asm("cvt.rna.tf32.f32 %0, %1;" : "=r"(u) : "f"(x));
    return u;
}

__device__ __forceinline__ void mma_tf32(float c[4], const unsigned a[4],
                                         unsigned b0, unsigned b1) {
    asm volatile(
        "mma.sync.aligned.m16n8k8.row.col.f32.tf32.tf32.f32 "
        "{%0,%1,%2,%3}, {%4,%5,%6,%7}, {%8,%9}, {%0,%1,%2,%3};"
        : "+f"(c[0]), "+f"(c[1]), "+f"(c[2]), "+f"(c[3])
        : "r"(a[0]), "r"(a[1]), "r"(a[2]), "r"(a[3]), "r"(b0), "r"(b1));
}

// exp(x) = 2^(x*log2e), n = rint, degree-5 poly for 2^f on [-0.5,0.5]
// (rel err ~2e-6). Avoids MUFU (which would bottleneck at 67M exps).
__device__ __forceinline__ float fexp(float x) {
    float y = x * 1.4426950408889634f;
    float n = rintf(y);
    float f = y - n;
    float p = 1.3333558146428443e-3f;
    p = fmaf(p, f, 9.6181291076284772e-3f);
    p = fmaf(p, f, 5.5504108664821580e-2f);
    p = fmaf(p, f, 2.4022650695910071e-1f);
    p = fmaf(p, f, 6.9314718055994531e-1f);
    p = fmaf(p, f, 1.0f);
    return __int_as_float(__float_as_int(p) + (__float2int_rn(n) << 23));
}

// ---------------------------------------------------------------------------
// Kernel 1: K/V projection.  k = x @ Wk^T + bk ; v = x @ Wv^T + bv
// grid 128 blocks x 256 threads; 64 rows per block.
// ---------------------------------------------------------------------------
__global__ void kv_proj(const float* __restrict__ x,
                        const float* __restrict__ Wk, const float* __restrict__ bk,
                        const float* __restrict__ Wv, const float* __restrict__ bv) {
    __shared__ float sX[64][33];
    __shared__ float sWk[64][33];
    __shared__ float sWv[64][33];

    const int rowbase = blockIdx.x * 64;
    const int f  = threadIdx.x & 63;
    const int rg = threadIdx.x >> 6;   // 0..3

    float accK[16], accV[16];
#pragma unroll
    for (int i = 0; i < 16; ++i) { accK[i] = 0.f; accV[i] = 0.f; }

    for (int ch = 0; ch < 8; ++ch) {
        __syncthreads();
#pragma unroll
        for (int it = 0; it < 8; ++it) {
            int i = threadIdx.x + it * 256;       // 0..2047
            int r = i >> 5, c = i & 31;
            sX [r][c] = x [(size_t)(rowbase + r) * DD + ch * 32 + c];
            sWk[r][c] = Wk[(size_t)r * DD + ch * 32 + c];
            sWv[r][c] = Wv[(size_t)r * DD + ch * 32 + c];
        }
        __syncthreads();
#pragma unroll
        for (int d = 0; d < 32; ++d) {
            float wk = sWk[f][d], wv = sWv[f][d];
#pragma unroll
            for (int i = 0; i < 16; ++i) {
                float xv = sX[rg + i * 4][d];
                accK[i] = fmaf(xv, wk, accK[i]);
                accV[i] = fmaf(xv, wv, accV[i]);
            }
        }
    }
    float bkf = bk[f], bvf = bv[f];
#pragma unroll
    for (int i = 0; i < 16; ++i) {
        int r = rowbase + rg + i * 4;
        g_k[(size_t)r * FF + f] = accK[i] + bkf;
        g_v[(size_t)r * FF + f] = accV[i] + bvf;
    }
}

// ---------------------------------------------------------------------------
// Kernel 2: per-node Q projection. q[n,f] = dot(x[n,:], Wq[n,f,:]) + bq[n,f]
// One block per node; HBM-bound on Wq (512 MB).
// ---------------------------------------------------------------------------
__global__ void q_proj(const float* __restrict__ x,
                       const float* __restrict__ Wq,
                       const float* __restrict__ bq) {
    __shared__ float sx[DD];
    const int n = blockIdx.x;
    sx[threadIdx.x] = x[(size_t)n * DD + threadIdx.x];
    __syncthreads();

    const int f = threadIdx.x >> 2;
    const int part = threadIdx.x & 3;

    const float4* w  = (const float4*)(Wq + ((size_t)n * FF + f) * DD + part * 64);
    const float4* xv = (const float4*)(sx + part * 64);

    float a0 = 0.f, a1 = 0.f, a2 = 0.f, a3 = 0.f;
#pragma unroll
    for (int i = 0; i < 16; i += 4) {
        float4 w0 = w[i + 0], w1 = w[i + 1], w2 = w[i + 2], w3 = w[i + 3];
        float4 x0 = xv[i + 0], x1 = xv[i + 1], x2 = xv[i + 2], x3 = xv[i + 3];
        a0 = fmaf(w0.x, x0.x, fmaf(w0.y, x0.y, fmaf(w0.z, x0.z, fmaf(w0.w, x0.w, a0))));
        a1 = fmaf(w1.x, x1.x, fmaf(w1.y, x1.y, fmaf(w1.z, x1.z, fmaf(w1.w, x1.w, a1))));
        a2 = fmaf(w2.x, x2.x, fmaf(w2.y, x2.y, fmaf(w2.z, x2.z, fmaf(w2.w, x2.w, a2))));
        a3 = fmaf(w3.x, x3.x, fmaf(w3.y, x3.y, fmaf(w3.z, x3.z, fmaf(w3.w, x3.w, a3))));
    }
    float a = (a0 + a1) + (a2 + a3);
    a += __shfl_xor_sync(0xffffffffu, a, 1);
    a += __shfl_xor_sync(0xffffffffu, a, 2);
    if (part == 0)
        g_q[(size_t)n * FF + f] = a + bq[(size_t)n * FF + f];
}

// ---------------------------------------------------------------------------
// Kernel 3: flash attention (tf32 mma, no max subtraction — scores are O(1)).
// grid (128 q-tiles, 4 kv-splits), 128 threads (4 warps x 16 query rows).
// ---------------------------------------------------------------------------
__global__ void attn_kernel() {
    // sK also serves as the P staging buffer between the two MMAs.
    __shared__ unsigned sK[64][68];   // pad 68: conflict-free B/A fragment LDS
    __shared__ unsigned sV[64][72];   // pad 72: conflict-free B fragment LDS

    const int qt = blockIdx.x;
    const int sp = blockIdx.y;
    const int warp = threadIdx.x >> 5;
    const int lane = threadIdx.x & 31;
    const int g = lane >> 2;      // groupID 0..7
    const int tig = lane & 3;     // threadID-in-group 0..3

    const int qrow = qt * 64 + warp * 16;

    // Q fragments (scale 1/sqrt(F)=1/8 folded in), tf32, persistent in regs.
    unsigned qa[8][4];
#pragma unroll
    for (int ko = 0; ko < 8; ++ko) {
        int d0 = ko * 8;
        qa[ko][0] = cvt_tf32(g_q[(size_t)(qrow + g)     * FF + d0 + tig]     * 0.125f);
        qa[ko][1] = cvt_tf32(g_q[(size_t)(qrow + g + 8) * FF + d0 + tig]     * 0.125f);
        qa[ko][2] = cvt_tf32(g_q[(size_t)(qrow + g)     * FF + d0 + tig + 4] * 0.125f);
        qa[ko][3] = cvt_tf32(g_q[(size_t)(qrow + g + 8) * FF + d0 + tig + 4] * 0.125f);
    }

    float o[8][4];
#pragma unroll
    for (int n = 0; n < 8; ++n)
#pragma unroll
        for (int r = 0; r < 4; ++r) o[n][r] = 0.f;
    float rs0 = 0.f, rs1 = 0.f;

    const int kbase = sp * KEYS_PER_SPLIT;

    for (int kt = 0; kt < TILES_PER_SPLIT; ++kt) {
        const int krow = kbase + kt * BK;
        const float* kptr = g_k + (size_t)krow * FF;
        const float* vptr = g_v + (size_t)krow * FF;

        // load K,V tile, convert to tf32 bits once
#pragma unroll
        for (int it = 0; it < 8; ++it) {
            int i = threadIdx.x + it * 128;   // 0..1023 float4 units
            int r = i >> 4, c = (i & 15) << 2;
            float4 kk = *(const float4*)(kptr + r * FF + c);
            float4 vv = *(const float4*)(vptr + r * FF + c);
            uint4 ku = make_uint4(cvt_tf32(kk.x), cvt_tf32(kk.y), cvt_tf32(kk.z), cvt_tf32(kk.w));
            uint4 vu = make_uint4(cvt_tf32(vv.x), cvt_tf32(vv.y), cvt_tf32(vv.z), cvt_tf32(vv.w));
            *(uint4*)&sK[r][c] = ku;
            *(uint4*)&sV[r][c] = vu;
        }
        __syncthreads();

        // S = (Q*scale) @ K^T : 16 x 64 per warp
        float s[8][4];
#pragma unroll
        for (int n = 0; n < 8; ++n)
#pragma unroll
            for (int r = 0; r < 4; ++r) s[n][r] = 0.f;

#pragma unroll
        for (int ko = 0; ko < 8; ++ko) {
#pragma unroll
            for (int n = 0; n < 8; ++n) {
                unsigned b0 = sK[n * 8 + g][ko * 8 + tig];
                unsigned b1 = sK[n * 8 + g][ko * 8 + tig + 4];
                mma_tf32(s[n], qa[ko], b0, b1);
            }
        }
        __syncthreads();   // everyone done reading sK before P overwrites it

        // P = exp(S); accumulate row sums; stage P (tf32) into sK region
        const int prow = warp * 16 + g;
#pragma unroll
        for (int n = 0; n < 8; ++n) {
            float p0 = fexp(s[n][0]);
            float p1 = fexp(s[n][1]);
            float p2 = fexp(s[n][2]);
            float p3 = fexp(s[n][3]);
            rs0 += p0 + p1;
            rs1 += p2 + p3;
            int col = n * 8 + 2 * tig;
            sK[prow][col]         = cvt_tf32(p0);
            sK[prow][col + 1]     = cvt_tf32(p1);
            sK[prow + 8][col]     = cvt_tf32(p2);
            sK[prow + 8][col + 1] = cvt_tf32(p3);
        }
        __syncthreads();

        // O += P @ V
#pragma unroll
        for (int ko = 0; ko < 8; ++ko) {
            unsigned pa[4];
            pa[0] = sK[warp * 16 + g][ko * 8 + tig];
            pa[1] = sK[warp * 16 + g + 8][ko * 8 + tig];
            pa[2] = sK[warp * 16 + g][ko * 8 + tig + 4];
            pa[3] = sK[warp * 16 + g + 8][ko * 8 + tig + 4];
#pragma unroll
            for (int n = 0; n < 8; ++n) {
                unsigned b0 = sV[ko * 8 + tig][n * 8 + g];
                unsigned b1 = sV[ko * 8 + tig + 4][n * 8 + g];
                mma_tf32(o[n], pa, b0, b1);
            }
        }
        __syncthreads();   // before next tile overwrites sK/sV
    }

    // reduce row sums across the 4 lanes of each quad (same g)
    rs0 += __shfl_xor_sync(0xffffffffu, rs0, 1);
    rs0 += __shfl_xor_sync(0xffffffffu, rs0, 2);
    rs1 += __shfl_xor_sync(0xffffffffu, rs1, 1);
    rs1 += __shfl_xor_sync(0xffffffffu, rs1, 2);

    float* op = g_op + ((size_t)sp * NN + qrow) * FF;
#pragma unroll
    for (int n = 0; n < 8; ++n) {
        int col = n * 8 + 2 * tig;
        *(float2*)&op[(size_t)g * FF + col]       = make_float2(o[n][0], o[n][1]);
        *(float2*)&op[(size_t)(g + 8) * FF + col] = make_float2(o[n][2], o[n][3]);
    }
    if (tig == 0) {
        g_rs[(size_t)sp * NN + qrow + g]     = rs0;
        g_rs[(size_t)sp * NN + qrow + g + 8] = rs1;
    }
}

// ---------------------------------------------------------------------------
// Kernel 4: merge split-KV partials:  out = sum_s O_s / sum_s rs_s
// ---------------------------------------------------------------------------
__global__ void combine_kernel(float* __restrict__ out) {
    int idx = blockIdx.x * 256 + threadIdx.x;   // 0 .. NN*FF-1
    int i = idx >> 6;
    float num = g_op[idx] + g_op[idx + NF] + g_op[idx + 2 * NF] + g_op[idx + 3 * NF];
    float den = g_rs[i] + g_rs[i + NN] + g_rs[i + 2 * NN] + g_rs[i + 3 * NN];
    out[idx] = num / den;
}

// ---------------------------------------------------------------------------
extern "C" void kernel_launch(void* const* d_in, const int* in_sizes, int n_in,
                              void* d_out, int out_size) {
    const float* x  = (const float*)d_in[0];
    const float* Wk = (const float*)d_in[1];
    const float* bk = (const float*)d_in[2];
    const float* Wv = (const float*)d_in[3];
    const float* bv = (const float*)d_in[4];
    const float* Wq = (const float*)d_in[5];
    const float* bq = (const float*)d_in[6];
    float* out = (float*)d_out;

    kv_proj<<<NN / 64, 256>>>(x, Wk, bk, Wv, bv);
    q_proj<<<NN, 256>>>(x, Wq, bq);
    attn_kernel<<<dim3(NN / 64, SPLITS), 128>>>();
    combine_kernel<<<(NN * FF) / 256, 256>>>(out);
}

// round 7
// speedup vs baseline: 1.0044x; 1.0044x over previous
#include <cuda_runtime.h>
#include <cuda_bf16.h>
#include <cstdint>

// Problem constants
#define NN 8192
#define DD 256
#define FF 64
#define SPLITS 4
#define KEYS_PER_SPLIT (NN / SPLITS)   // 2048
#define BK 64
#define TILES_PER_SPLIT (KEYS_PER_SPLIT / BK) // 32
#define NF (NN * FF)

// Scratch (device globals; no allocation allowed)
__device__ float g_k[NN * FF];
__device__ float g_v[NN * FF];
__device__ float g_q[NN * FF];
__device__ float g_op[SPLITS * NN * FF];   // partial numerators
__device__ float g_rs[SPLITS * NN];        // partial exp-sums

// ---------------------------------------------------------------------------
// helpers
// ---------------------------------------------------------------------------
__device__ __forceinline__ unsigned cvt_tf32(float x) {
    unsigned u;
    asm("cvt.rna.tf32.f32 %0, %1;" : "=r"(u) : "f"(x));
    return u;
}

__device__ __forceinline__ void mma_tf32(float c[4], const unsigned a[4],
                                         unsigned b0, unsigned b1) {
    asm volatile(
        "mma.sync.aligned.m16n8k8.row.col.f32.tf32.tf32.f32 "
        "{%0,%1,%2,%3}, {%4,%5,%6,%7}, {%8,%9}, {%0,%1,%2,%3};"
        : "+f"(c[0]), "+f"(c[1]), "+f"(c[2]), "+f"(c[3])
        : "r"(a[0]), "r"(a[1]), "r"(a[2]), "r"(a[3]), "r"(b0), "r"(b1));
}

// exp(x) = 2^(x*log2e), n = rint, degree-5 poly for 2^f on [-0.5,0.5]
// (rel err ~2e-6). Avoids MUFU (which would bottleneck at 67M exps).
__device__ __forceinline__ float fexp(float x) {
    float y = x * 1.4426950408889634f;
    float n = rintf(y);
    float f = y - n;
    float p = 1.3333558146428443e-3f;
    p = fmaf(p, f, 9.6181291076284772e-3f);
    p = fmaf(p, f, 5.5504108664821580e-2f);
    p = fmaf(p, f, 2.4022650695910071e-1f);
    p = fmaf(p, f, 6.9314718055994531e-1f);
    p = fmaf(p, f, 1.0f);
    return __int_as_float(__float_as_int(p) + (__float2int_rn(n) << 23));
}

// ---------------------------------------------------------------------------
// Kernel 1: K/V projection.  k = x @ Wk^T + bk ; v = x @ Wv^T + bv
// grid 128 blocks x 256 threads; 64 rows per block.
// ---------------------------------------------------------------------------
__global__ void kv_proj(const float* __restrict__ x,
                        const float* __restrict__ Wk, const float* __restrict__ bk,
                        const float* __restrict__ Wv, const float* __restrict__ bv) {
    __shared__ float sX[64][33];
    __shared__ float sWk[64][33];
    __shared__ float sWv[64][33];

    const int rowbase = blockIdx.x * 64;
    const int f  = threadIdx.x & 63;
    const int rg = threadIdx.x >> 6;   // 0..3

    float accK[16], accV[16];
#pragma unroll
    for (int i = 0; i < 16; ++i) { accK[i] = 0.f; accV[i] = 0.f; }

    for (int ch = 0; ch < 8; ++ch) {
        __syncthreads();
#pragma unroll
        for (int it = 0; it < 8; ++it) {
            int i = threadIdx.x + it * 256;       // 0..2047
            int r = i >> 5, c = i & 31;
            sX [r][c] = x [(size_t)(rowbase + r) * DD + ch * 32 + c];
            sWk[r][c] = Wk[(size_t)r * DD + ch * 32 + c];
            sWv[r][c] = Wv[(size_t)r * DD + ch * 32 + c];
        }
        __syncthreads();
#pragma unroll
        for (int d = 0; d < 32; ++d) {
            float wk = sWk[f][d], wv = sWv[f][d];
#pragma unroll
            for (int i = 0; i < 16; ++i) {
                float xv = sX[rg + i * 4][d];
                accK[i] = fmaf(xv, wk, accK[i]);
                accV[i] = fmaf(xv, wv, accV[i]);
            }
        }
    }
    float bkf = bk[f], bvf = bv[f];
#pragma unroll
    for (int i = 0; i < 16; ++i) {
        int r = rowbase + rg + i * 4;
        g_k[(size_t)r * FF + f] = accK[i] + bkf;
        g_v[(size_t)r * FF + f] = accV[i] + bvf;
    }
}

// ---------------------------------------------------------------------------
// Kernel 2: per-node Q projection. q[n,f] = dot(x[n,:], Wq[n,f,:]) + bq[n,f]
// One block per node; HBM-bound on Wq (512 MB).
// ---------------------------------------------------------------------------
__global__ void q_proj(const float* __restrict__ x,
                       const float* __restrict__ Wq,
                       const float* __restrict__ bq) {
    __shared__ float sx[DD];
    const int n = blockIdx.x;
    sx[threadIdx.x] = x[(size_t)n * DD + threadIdx.x];
    __syncthreads();

    const int f = threadIdx.x >> 2;
    const int part = threadIdx.x & 3;

    const float4* w  = (const float4*)(Wq + ((size_t)n * FF + f) * DD + part * 64);
    const float4* xv = (const float4*)(sx + part * 64);

    float a0 = 0.f, a1 = 0.f, a2 = 0.f, a3 = 0.f;
#pragma unroll
    for (int i = 0; i < 16; i += 4) {
        float4 w0 = w[i + 0], w1 = w[i + 1], w2 = w[i + 2], w3 = w[i + 3];
        float4 x0 = xv[i + 0], x1 = xv[i + 1], x2 = xv[i + 2], x3 = xv[i + 3];
        a0 = fmaf(w0.x, x0.x, fmaf(w0.y, x0.y, fmaf(w0.z, x0.z, fmaf(w0.w, x0.w, a0))));
        a1 = fmaf(w1.x, x1.x, fmaf(w1.y, x1.y, fmaf(w1.z, x1.z, fmaf(w1.w, x1.w, a1))));
        a2 = fmaf(w2.x, x2.x, fmaf(w2.y, x2.y, fmaf(w2.z, x2.z, fmaf(w2.w, x2.w, a2))));
        a3 = fmaf(w3.x, x3.x, fmaf(w3.y, x3.y, fmaf(w3.z, x3.z, fmaf(w3.w, x3.w, a3))));
    }
    float a = (a0 + a1) + (a2 + a3);
    a += __shfl_xor_sync(0xffffffffu, a, 1);
    a += __shfl_xor_sync(0xffffffffu, a, 2);
    if (part == 0)
        g_q[(size_t)n * FF + f] = a + bq[(size_t)n * FF + f];
}

// ---------------------------------------------------------------------------
// Kernel 3: flash attention (tf32 mma, no max subtraction — scores are O(1)).
// grid (128 q-tiles, 4 kv-splits), 128 threads (4 warps x 16 query rows).
// ---------------------------------------------------------------------------
__global__ void attn_kernel() {
    // sK also serves as the P staging buffer between the two MMAs.
    __shared__ unsigned sK[64][68];   // pad 68: conflict-free B/A fragment LDS
    __shared__ unsigned sV[64][72];   // pad 72: conflict-free B fragment LDS

    const int qt = blockIdx.x;
    const int sp = blockIdx.y;
    const int warp = threadIdx.x >> 5;
    const int lane = threadIdx.x & 31;
    const int g = lane >> 2;      // groupID 0..7
    const int tig = lane & 3;     // threadID-in-group 0..3

    const int qrow = qt * 64 + warp * 16;

    // Q fragments (scale 1/sqrt(F)=1/8 folded in), tf32, persistent in regs.
    unsigned qa[8][4];
#pragma unroll
    for (int ko = 0; ko < 8; ++ko) {
        int d0 = ko * 8;
        qa[ko][0] = cvt_tf32(g_q[(size_t)(qrow + g)     * FF + d0 + tig]     * 0.125f);
        qa[ko][1] = cvt_tf32(g_q[(size_t)(qrow + g + 8) * FF + d0 + tig]     * 0.125f);
        qa[ko][2] = cvt_tf32(g_q[(size_t)(qrow + g)     * FF + d0 + tig + 4] * 0.125f);
        qa[ko][3] = cvt_tf32(g_q[(size_t)(qrow + g + 8) * FF + d0 + tig + 4] * 0.125f);
    }

    float o[8][4];
#pragma unroll
    for (int n = 0; n < 8; ++n)
#pragma unroll
        for (int r = 0; r < 4; ++r) o[n][r] = 0.f;
    float rs0 = 0.f, rs1 = 0.f;

    const int kbase = sp * KEYS_PER_SPLIT;

    for (int kt = 0; kt < TILES_PER_SPLIT; ++kt) {
        const int krow = kbase + kt * BK;
        const float* kptr = g_k + (size_t)krow * FF;
        const float* vptr = g_v + (size_t)krow * FF;

        // load K,V tile, convert to tf32 bits once
#pragma unroll
        for (int it = 0; it < 8; ++it) {
            int i = threadIdx.x + it * 128;   // 0..1023 float4 units
            int r = i >> 4, c = (i & 15) << 2;
            float4 kk = *(const float4*)(kptr + r * FF + c);
            float4 vv = *(const float4*)(vptr + r * FF + c);
            uint4 ku = make_uint4(cvt_tf32(kk.x), cvt_tf32(kk.y), cvt_tf32(kk.z), cvt_tf32(kk.w));
            uint4 vu = make_uint4(cvt_tf32(vv.x), cvt_tf32(vv.y), cvt_tf32(vv.z), cvt_tf32(vv.w));
            *(uint4*)&sK[r][c] = ku;
            *(uint4*)&sV[r][c] = vu;
        }
        __syncthreads();

        // S = (Q*scale) @ K^T : 16 x 64 per warp
        float s[8][4];
#pragma unroll
        for (int n = 0; n < 8; ++n)
#pragma unroll
            for (int r = 0; r < 4; ++r) s[n][r] = 0.f;

#pragma unroll
        for (int ko = 0; ko < 8; ++ko) {
#pragma unroll
            for (int n = 0; n < 8; ++n) {
                unsigned b0 = sK[n * 8 + g][ko * 8 + tig];
                unsigned b1 = sK[n * 8 + g][ko * 8 + tig + 4];
                mma_tf32(s[n], qa[ko], b0, b1);
            }
        }
        __syncthreads();   // everyone done reading sK before P overwrites it

        // P = exp(S); accumulate row sums; stage P (tf32) into sK region
        const int prow = warp * 16 + g;
#pragma unroll
        for (int n = 0; n < 8; ++n) {
            float p0 = fexp(s[n][0]);
            float p1 = fexp(s[n][1]);
            float p2 = fexp(s[n][2]);
            float p3 = fexp(s[n][3]);
            rs0 += p0 + p1;
            rs1 += p2 + p3;
            int col = n * 8 + 2 * tig;
            sK[prow][col]         = cvt_tf32(p0);
            sK[prow][col + 1]     = cvt_tf32(p1);
            sK[prow + 8][col]     = cvt_tf32(p2);
            sK[prow + 8][col + 1] = cvt_tf32(p3);
        }
        __syncthreads();

        // O += P @ V
#pragma unroll
        for (int ko = 0; ko < 8; ++ko) {
            unsigned pa[4];
            pa[0] = sK[warp * 16 + g][ko * 8 + tig];
            pa[1] = sK[warp * 16 + g + 8][ko * 8 + tig];
            pa[2] = sK[warp * 16 + g][ko * 8 + tig + 4];
            pa[3] = sK[warp * 16 + g + 8][ko * 8 + tig + 4];
#pragma unroll
            for (int n = 0; n < 8; ++n) {
                unsigned b0 = sV[ko * 8 + tig][n * 8 + g];
                unsigned b1 = sV[ko * 8 + tig + 4][n * 8 + g];
                mma_tf32(o[n], pa, b0, b1);
            }
        }
        __syncthreads();   // before next tile overwrites sK/sV
    }

    // reduce row sums across the 4 lanes of each quad (same g)
    rs0 += __shfl_xor_sync(0xffffffffu, rs0, 1);
    rs0 += __shfl_xor_sync(0xffffffffu, rs0, 2);
    rs1 += __shfl_xor_sync(0xffffffffu, rs1, 1);
    rs1 += __shfl_xor_sync(0xffffffffu, rs1, 2);

    float* op = g_op + ((size_t)sp * NN + qrow) * FF;
#pragma unroll
    for (int n = 0; n < 8; ++n) {
        int col = n * 8 + 2 * tig;
        *(float2*)&op[(size_t)g * FF + col]       = make_float2(o[n][0], o[n][1]);
        *(float2*)&op[(size_t)(g + 8) * FF + col] = make_float2(o[n][2], o[n][3]);
    }
    if (tig == 0) {
        g_rs[(size_t)sp * NN + qrow + g]     = rs0;
        g_rs[(size_t)sp * NN + qrow + g + 8] = rs1;
    }
}

// ---------------------------------------------------------------------------
// Kernel 4: merge split-KV partials:  out = sum_s O_s / sum_s rs_s
// ---------------------------------------------------------------------------
__global__ void combine_kernel(float* __restrict__ out) {
    int idx = blockIdx.x * 256 + threadIdx.x;   // 0 .. NN*FF-1
    int i = idx >> 6;
    float num = g_op[idx] + g_op[idx + NF] + g_op[idx + 2 * NF] + g_op[idx + 3 * NF];
    float den = g_rs[i] + g_rs[i + NN] + g_rs[i + 2 * NN] + g_rs[i + 3 * NN];
    out[idx] = num / den;
}

// ---------------------------------------------------------------------------
extern "C" void kernel_launch(void* const* d_in, const int* in_sizes, int n_in,
                              void* d_out, int out_size) {
    const float* x  = (const float*)d_in[0];
    const float* Wk = (const float*)d_in[1];
    const float* bk = (const float*)d_in[2];
    const float* Wv = (const float*)d_in[3];
    const float* bv = (const float*)d_in[4];
    const float* Wq = (const float*)d_in[5];
    const float* bq = (const float*)d_in[6];
    float* out = (float*)d_out;

    kv_proj<<<NN / 64, 256>>>(x, Wk, bk, Wv, bv);
    q_proj<<<NN, 256>>>(x, Wq, bq);
    attn_kernel<<<dim3(NN / 64, SPLITS), 128>>>();
    combine_kernel<<<(NN * FF) / 256, 256>>>(out);
}

// round 8
// speedup vs baseline: 1.0873x; 1.0826x over previous
#include <cuda_runtime.h>
#include <cuda_fp16.h>
#include <cstdint>

// Problem constants
#define NN 8192
#define DD 256
#define FF 64
#define SPLITS 4
#define KEYS_PER_SPLIT (NN / SPLITS)   // 2048
#define BK 64
#define TILES_PER_SPLIT (KEYS_PER_SPLIT / BK) // 32
#define NF (NN * FF)

// Scratch (device globals; no allocation allowed)
__device__ float g_k[NN * FF];
__device__ float g_v[NN * FF];
__device__ float g_q[NN * FF];
__device__ float g_op[SPLITS * NN * FF];   // partial numerators
__device__ float g_rs[SPLITS * NN];        // partial exp-sums

// ---------------------------------------------------------------------------
// helpers
// ---------------------------------------------------------------------------
__device__ __forceinline__ uint32_t packh2(float a, float b) {
    __half2 h = __floats2half2_rn(a, b);
    return *reinterpret_cast<uint32_t*>(&h);
}

__device__ __forceinline__ void mma_f16(float c[4], const uint32_t a[4],
                                        uint32_t b0, uint32_t b1) {
    asm volatile(
        "mma.sync.aligned.m16n8k16.row.col.f32.f16.f16.f32 "
        "{%0,%1,%2,%3}, {%4,%5,%6,%7}, {%8,%9}, {%0,%1,%2,%3};"
        : "+f"(c[0]), "+f"(c[1]), "+f"(c[2]), "+f"(c[3])
        : "r"(a[0]), "r"(a[1]), "r"(a[2]), "r"(a[3]), "r"(b0), "r"(b1));
}

__device__ __forceinline__ void ldsm_x4(uint32_t& r0, uint32_t& r1,
                                        uint32_t& r2, uint32_t& r3, uint32_t addr) {
    asm volatile("ldmatrix.sync.aligned.m8n8.x4.shared.b16 {%0,%1,%2,%3}, [%4];"
                 : "=r"(r0), "=r"(r1), "=r"(r2), "=r"(r3) : "r"(addr));
}

__device__ __forceinline__ void ldsm_x4_t(uint32_t& r0, uint32_t& r1,
                                          uint32_t& r2, uint32_t& r3, uint32_t addr) {
    asm volatile("ldmatrix.sync.aligned.m8n8.x4.trans.shared.b16 {%0,%1,%2,%3}, [%4];"
                 : "=r"(r0), "=r"(r1), "=r"(r2), "=r"(r3) : "r"(addr));
}

// exp(x) = 2^(x*log2e), n = rint, degree-5 poly for 2^f on [-0.5,0.5]
// (rel err ~2e-6). Avoids MUFU (would bottleneck at 67M exps).
__device__ __forceinline__ float fexp(float x) {
    float y = x * 1.4426950408889634f;
    float n = rintf(y);
    float f = y - n;
    float p = 1.3333558146428443e-3f;
    p = fmaf(p, f, 9.6181291076284772e-3f);
    p = fmaf(p, f, 5.5504108664821580e-2f);
    p = fmaf(p, f, 2.4022650695910071e-1f);
    p = fmaf(p, f, 6.9314718055994531e-1f);
    p = fmaf(p, f, 1.0f);
    return __int_as_float(__float_as_int(p) + (__float2int_rn(n) << 23));
}

// ---------------------------------------------------------------------------
// Kernel 1: K/V projection.  k = x @ Wk^T + bk ; v = x @ Wv^T + bv
// ---------------------------------------------------------------------------
__global__ void kv_proj(const float* __restrict__ x,
                        const float* __restrict__ Wk, const float* __restrict__ bk,
                        const float* __restrict__ Wv, const float* __restrict__ bv) {
    __shared__ float sX[64][33];
    __shared__ float sWk[64][33];
    __shared__ float sWv[64][33];

    const int rowbase = blockIdx.x * 64;
    const int f  = threadIdx.x & 63;
    const int rg = threadIdx.x >> 6;   // 0..3

    float accK[16], accV[16];
#pragma unroll
    for (int i = 0; i < 16; ++i) { accK[i] = 0.f; accV[i] = 0.f; }

    for (int ch = 0; ch < 8; ++ch) {
        __syncthreads();
#pragma unroll
        for (int it = 0; it < 8; ++it) {
            int i = threadIdx.x + it * 256;       // 0..2047
            int r = i >> 5, c = i & 31;
            sX [r][c] = x [(size_t)(rowbase + r) * DD + ch * 32 + c];
            sWk[r][c] = Wk[(size_t)r * DD + ch * 32 + c];
            sWv[r][c] = Wv[(size_t)r * DD + ch * 32 + c];
        }
        __syncthreads();
#pragma unroll
        for (int d = 0; d < 32; ++d) {
            float wk = sWk[f][d], wv = sWv[f][d];
#pragma unroll
            for (int i = 0; i < 16; ++i) {
                float xv = sX[rg + i * 4][d];
                accK[i] = fmaf(xv, wk, accK[i]);
                accV[i] = fmaf(xv, wv, accV[i]);
            }
        }
    }
    float bkf = bk[f], bvf = bv[f];
#pragma unroll
    for (int i = 0; i < 16; ++i) {
        int r = rowbase + rg + i * 4;
        g_k[(size_t)r * FF + f] = accK[i] + bkf;
        g_v[(size_t)r * FF + f] = accV[i] + bvf;
    }
}

// ---------------------------------------------------------------------------
// Kernel 2: per-node Q projection (HBM-bound on 512 MB Wq).
// ---------------------------------------------------------------------------
__global__ void q_proj(const float* __restrict__ x,
                       const float* __restrict__ Wq,
                       const float* __restrict__ bq) {
    __shared__ float sx[DD];
    const int n = blockIdx.x;
    sx[threadIdx.x] = x[(size_t)n * DD + threadIdx.x];
    __syncthreads();

    const int f = threadIdx.x >> 2;
    const int part = threadIdx.x & 3;

    const float4* w  = (const float4*)(Wq + ((size_t)n * FF + f) * DD + part * 64);
    const float4* xv = (const float4*)(sx + part * 64);

    float a0 = 0.f, a1 = 0.f, a2 = 0.f, a3 = 0.f;
#pragma unroll
    for (int i = 0; i < 16; i += 4) {
        float4 w0 = w[i + 0], w1 = w[i + 1], w2 = w[i + 2], w3 = w[i + 3];
        float4 x0 = xv[i + 0], x1 = xv[i + 1], x2 = xv[i + 2], x3 = xv[i + 3];
        a0 = fmaf(w0.x, x0.x, fmaf(w0.y, x0.y, fmaf(w0.z, x0.z, fmaf(w0.w, x0.w, a0))));
        a1 = fmaf(w1.x, x1.x, fmaf(w1.y, x1.y, fmaf(w1.z, x1.z, fmaf(w1.w, x1.w, a1))));
        a2 = fmaf(w2.x, x2.x, fmaf(w2.y, x2.y, fmaf(w2.z, x2.z, fmaf(w2.w, x2.w, a2))));
        a3 = fmaf(w3.x, x3.x, fmaf(w3.y, x3.y, fmaf(w3.z, x3.z, fmaf(w3.w, x3.w, a3))));
    }
    float a = (a0 + a1) + (a2 + a3);
    a += __shfl_xor_sync(0xffffffffu, a, 1);
    a += __shfl_xor_sync(0xffffffffu, a, 2);
    if (part == 0)
        g_q[(size_t)n * FF + f] = a + bq[(size_t)n * FF + f];
}

// ---------------------------------------------------------------------------
// Kernel 3: flash attention, fp16 m16n8k16 MMA (fp32 accum).
//   fp16 mantissa == tf32 mantissa (10 bits) and all operands are O(1),
//   so accuracy matches the previous tf32 version.
//   - K fragments via ldmatrix.x4, V fragments via ldmatrix.x4.trans
//   - P reused register-direct (S C-fragment == PV A-fragment layout)
// grid (128 q-tiles, 4 kv-splits), 128 threads (4 warps x 16 query rows).
// ---------------------------------------------------------------------------
__global__ void attn_kernel() {
    __shared__ __half sK[64][72];   // 72-half rows: conflict-free LDSM
    __shared__ __half sV[64][72];

    const int qt = blockIdx.x;
    const int sp = blockIdx.y;
    const int warp = threadIdx.x >> 5;
    const int lane = threadIdx.x & 31;
    const int g = lane >> 2;      // groupID 0..7
    const int tig = lane & 3;     // threadID-in-group 0..3

    const int qrow = qt * 64 + warp * 16;

    // Q fragments fp16 (scale 1/8 folded in), persistent in regs.
    // m16n8k16 A: a0=(g,2t..2t+1) a1=(g+8,2t..) a2=(g,2t+8..) a3=(g+8,2t+8..)
    uint32_t qa[4][4];
#pragma unroll
    for (int ko = 0; ko < 4; ++ko) {
        int c0 = ko * 16 + 2 * tig;
        float2 f00 = *(const float2*)&g_q[(size_t)(qrow + g)     * FF + c0];
        float2 f10 = *(const float2*)&g_q[(size_t)(qrow + g + 8) * FF + c0];
        float2 f01 = *(const float2*)&g_q[(size_t)(qrow + g)     * FF + c0 + 8];
        float2 f11 = *(const float2*)&g_q[(size_t)(qrow + g + 8) * FF + c0 + 8];
        qa[ko][0] = packh2(f00.x * 0.125f, f00.y * 0.125f);
        qa[ko][1] = packh2(f10.x * 0.125f, f10.y * 0.125f);
        qa[ko][2] = packh2(f01.x * 0.125f, f01.y * 0.125f);
        qa[ko][3] = packh2(f11.x * 0.125f, f11.y * 0.125f);
    }

    float o[8][4];
#pragma unroll
    for (int n = 0; n < 8; ++n)
#pragma unroll
        for (int r = 0; r < 4; ++r) o[n][r] = 0.f;
    float rs0 = 0.f, rs1 = 0.f;

    const uint32_t sK_u = (uint32_t)__cvta_generic_to_shared(&sK[0][0]);
    const uint32_t sV_u = (uint32_t)__cvta_generic_to_shared(&sV[0][0]);

    // lane-constant LDSM addressing pieces
    const int blk = lane >> 3, r8 = lane & 7;
    const int s_row_off = ((blk >> 1) << 3) + r8;   // S: row = n*8 + this
    const int s_col_off = (blk & 1) << 3;           // S: col = kb + this
    const int v_row_off = ((blk & 1) << 3) + r8;    // V: row = kb + this
    const int v_col_off = (blk >> 1) << 3;          // V: col = n*8 + this

    const int kbase = sp * KEYS_PER_SPLIT;

    for (int kt = 0; kt < TILES_PER_SPLIT; ++kt) {
        const int krow = kbase + kt * BK;
        const float* kptr = g_k + (size_t)krow * FF;
        const float* vptr = g_v + (size_t)krow * FF;

        // stage K,V tile as fp16
#pragma unroll
        for (int it = 0; it < 8; ++it) {
            int i = threadIdx.x + it * 128;   // 0..1023 float4 units
            int r = i >> 4, c = (i & 15) << 2;
            float4 kk = *(const float4*)(kptr + r * FF + c);
            float4 vv = *(const float4*)(vptr + r * FF + c);
            *(uint2*)&sK[r][c] = make_uint2(packh2(kk.x, kk.y), packh2(kk.z, kk.w));
            *(uint2*)&sV[r][c] = make_uint2(packh2(vv.x, vv.y), packh2(vv.z, vv.w));
        }
        __syncthreads();

        // S = (Q*scale) @ K^T : 16 x 64 per warp
        float s[8][4];
#pragma unroll
        for (int n = 0; n < 8; ++n)
#pragma unroll
            for (int r = 0; r < 4; ++r) s[n][r] = 0.f;

#pragma unroll
        for (int ko = 0; ko < 4; ++ko) {
            const int kb = ko << 4;
#pragma unroll
            for (int n2 = 0; n2 < 4; ++n2) {
                const int n = n2 << 1;
                uint32_t a = sK_u +
                    (uint32_t)(((n << 3) + s_row_off) * 72 + kb + s_col_off) * 2u;
                uint32_t b0, b1, b2, b3;
                ldsm_x4(b0, b1, b2, b3, a);
                mma_f16(s[n],     qa[ko], b0, b1);
                mma_f16(s[n + 1], qa[ko], b2, b3);
            }
        }

        // P = exp(S) register-direct into A fragments; O += P @ V
#pragma unroll
        for (int ko = 0; ko < 4; ++ko) {
            const int kb = ko << 4;
            // build P A-fragment for key block [16ko, 16ko+16)
            float p00 = fexp(s[2 * ko][0]),     p01 = fexp(s[2 * ko][1]);
            float p10 = fexp(s[2 * ko][2]),     p11 = fexp(s[2 * ko][3]);
            float q00 = fexp(s[2 * ko + 1][0]), q01 = fexp(s[2 * ko + 1][1]);
            float q10 = fexp(s[2 * ko + 1][2]), q11 = fexp(s[2 * ko + 1][3]);
            rs0 += (p00 + p01) + (q00 + q01);
            rs1 += (p10 + p11) + (q10 + q11);
            uint32_t pa[4];
            pa[0] = packh2(p00, p01);
            pa[1] = packh2(p10, p11);
            pa[2] = packh2(q00, q01);
            pa[3] = packh2(q10, q11);
#pragma unroll
            for (int n2 = 0; n2 < 4; ++n2) {
                const int n = n2 << 1;
                uint32_t a = sV_u +
                    (uint32_t)((kb + v_row_off) * 72 + (n << 3) + v_col_off) * 2u;
                uint32_t b0, b1, b2, b3;
                ldsm_x4_t(b0, b1, b2, b3, a);
                mma_f16(o[n],     pa, b0, b1);
                mma_f16(o[n + 1], pa, b2, b3);
            }
        }
        __syncthreads();   // before next tile overwrites sK/sV
    }

    // reduce row sums across the 4 lanes of each quad (same g)
    rs0 += __shfl_xor_sync(0xffffffffu, rs0, 1);
    rs0 += __shfl_xor_sync(0xffffffffu, rs0, 2);
    rs1 += __shfl_xor_sync(0xffffffffu, rs1, 1);
    rs1 += __shfl_xor_sync(0xffffffffu, rs1, 2);

    float* op = g_op + ((size_t)sp * NN + qrow) * FF;
#pragma unroll
    for (int n = 0; n < 8; ++n) {
        int col = n * 8 + 2 * tig;
        *(float2*)&op[(size_t)g * FF + col]       = make_float2(o[n][0], o[n][1]);
        *(float2*)&op[(size_t)(g + 8) * FF + col] = make_float2(o[n][2], o[n][3]);
    }
    if (tig == 0) {
        g_rs[(size_t)sp * NN + qrow + g]     = rs0;
        g_rs[(size_t)sp * NN + qrow + g + 8] = rs1;
    }
}

// ---------------------------------------------------------------------------
// Kernel 4: merge split-KV partials:  out = sum_s O_s / sum_s rs_s
// ---------------------------------------------------------------------------
__global__ void combine_kernel(float* __restrict__ out) {
    int idx = blockIdx.x * 256 + threadIdx.x;   // 0 .. NN*FF-1
    int i = idx >> 6;
    float num = g_op[idx] + g_op[idx + NF] + g_op[idx + 2 * NF] + g_op[idx + 3 * NF];
    float den = g_rs[i] + g_rs[i + NN] + g_rs[i + 2 * NN] + g_rs[i + 3 * NN];
    out[idx] = num / den;
}

// ---------------------------------------------------------------------------
extern "C" void kernel_launch(void* const* d_in, const int* in_sizes, int n_in,
                              void* d_out, int out_size) {
    const float* x  = (const float*)d_in[0];
    const float* Wk = (const float*)d_in[1];
    const float* bk = (const float*)d_in[2];
    const float* Wv = (const float*)d_in[3];
    const float* bv = (const float*)d_in[4];
    const float* Wq = (const float*)d_in[5];
    const float* bq = (const float*)d_in[6];
    float* out = (float*)d_out;

    kv_proj<<<NN / 64, 256>>>(x, Wk, bk, Wv, bv);
    q_proj<<<NN, 256>>>(x, Wq, bq);
    attn_kernel<<<dim3(NN / 64, SPLITS), 128>>>();
    combine_kernel<<<(NN * FF) / 256, 256>>>(out);
}

// round 9
// speedup vs baseline: 1.3471x; 1.2389x over previous
#include <cuda_runtime.h>
#include <cuda_fp16.h>
#include <cstdint>

// Problem constants
#define NN 8192
#define DD 256
#define FF 64
#define SPLITS 4
#define KEYS_PER_SPLIT (NN / SPLITS)            // 2048
#define BK 64
#define TILES_PER_SPLIT (KEYS_PER_SPLIT / BK)   // 32
#define QROWS 128                               // q rows per attn block
#define NF (NN * FF)

// Scratch (device globals; no allocation allowed)
__device__ __half g_kh[NN * FF];           // K, fp16
__device__ __half g_vh[NN * FF];           // V, fp16
__device__ __half g_qh[NN * FF];           // Q * 1/sqrt(F), fp16
__device__ float  g_op[SPLITS * NN * FF];  // partial numerators
__device__ float  g_rs[SPLITS * NN];       // partial exp-sums

// ---------------------------------------------------------------------------
// helpers
// ---------------------------------------------------------------------------
__device__ __forceinline__ uint32_t packh2(float a, float b) {
    __half2 h = __floats2half2_rn(a, b);
    return *reinterpret_cast<uint32_t*>(&h);
}

__device__ __forceinline__ void mma_f16(float c[4], const uint32_t a[4],
                                        uint32_t b0, uint32_t b1) {
    asm volatile(
        "mma.sync.aligned.m16n8k16.row.col.f32.f16.f16.f32 "
        "{%0,%1,%2,%3}, {%4,%5,%6,%7}, {%8,%9}, {%0,%1,%2,%3};"
        : "+f"(c[0]), "+f"(c[1]), "+f"(c[2]), "+f"(c[3])
        : "r"(a[0]), "r"(a[1]), "r"(a[2]), "r"(a[3]), "r"(b0), "r"(b1));
}

__device__ __forceinline__ void ldsm_x4(uint32_t& r0, uint32_t& r1,
                                        uint32_t& r2, uint32_t& r3, uint32_t addr) {
    asm volatile("ldmatrix.sync.aligned.m8n8.x4.shared.b16 {%0,%1,%2,%3}, [%4];"
                 : "=r"(r0), "=r"(r1), "=r"(r2), "=r"(r3) : "r"(addr));
}

__device__ __forceinline__ void ldsm_x4_t(uint32_t& r0, uint32_t& r1,
                                          uint32_t& r2, uint32_t& r3, uint32_t addr) {
    asm volatile("ldmatrix.sync.aligned.m8n8.x4.trans.shared.b16 {%0,%1,%2,%3}, [%4];"
                 : "=r"(r0), "=r"(r1), "=r"(r2), "=r"(r3) : "r"(addr));
}

__device__ __forceinline__ void cp16(uint32_t smem_dst, const void* gmem_src) {
    asm volatile("cp.async.cg.shared.global [%0], [%1], 16;"
                 :: "r"(smem_dst), "l"(gmem_src));
}
__device__ __forceinline__ void cp_commit() {
    asm volatile("cp.async.commit_group;");
}
__device__ __forceinline__ void cp_wait0() {
    asm volatile("cp.async.wait_group 0;");
}

// exp(x) via 2^(x*log2e), magic-constant rounding (no rint/F2I), deg-5 poly.
// Valid for |x| << 2^22; scores here are O(1). rel err ~2e-6.
__device__ __forceinline__ float fexp(float x) {
    const float L2E = 1.4426950408889634f;
    const float MAGIC = 12582912.0f;  // 2^23 + 2^22
    float y = fmaf(x, L2E, MAGIC);
    int   n = __float_as_int(y);      // low bits hold rint(x*L2E)
    float r = y - MAGIC;
    float f = fmaf(x, L2E, -r);       // fractional part in [-0.5, 0.5]
    float p = 1.3333558146428443e-3f;
    p = fmaf(p, f, 9.6181291076284772e-3f);
    p = fmaf(p, f, 5.5504108664821580e-2f);
    p = fmaf(p, f, 2.4022650695910071e-1f);
    p = fmaf(p, f, 6.9314718055994531e-1f);
    p = fmaf(p, f, 1.0f);
    return __int_as_float(__float_as_int(p) + (n << 23));
}

// ---------------------------------------------------------------------------
// Kernel 1: K/V projection -> fp16.  k = x @ Wk^T + bk ; v = x @ Wv^T + bv
// ---------------------------------------------------------------------------
__global__ void kv_proj(const float* __restrict__ x,
                        const float* __restrict__ Wk, const float* __restrict__ bk,
                        const float* __restrict__ Wv, const float* __restrict__ bv) {
    __shared__ float sX[64][33];
    __shared__ float sWk[64][33];
    __shared__ float sWv[64][33];

    const int rowbase = blockIdx.x * 64;
    const int f  = threadIdx.x & 63;
    const int rg = threadIdx.x >> 6;   // 0..3

    float accK[16], accV[16];
#pragma unroll
    for (int i = 0; i < 16; ++i) { accK[i] = 0.f; accV[i] = 0.f; }

    for (int ch = 0; ch < 8; ++ch) {
        __syncthreads();
#pragma unroll
        for (int it = 0; it < 8; ++it) {
            int i = threadIdx.x + it * 256;       // 0..2047
            int r = i >> 5, c = i & 31;
            sX [r][c] = x [(size_t)(rowbase + r) * DD + ch * 32 + c];
            sWk[r][c] = Wk[(size_t)r * DD + ch * 32 + c];
            sWv[r][c] = Wv[(size_t)r * DD + ch * 32 + c];
        }
        __syncthreads();
#pragma unroll
        for (int d = 0; d < 32; ++d) {
            float wk = sWk[f][d], wv = sWv[f][d];
#pragma unroll
            for (int i = 0; i < 16; ++i) {
                float xv = sX[rg + i * 4][d];
                accK[i] = fmaf(xv, wk, accK[i]);
                accV[i] = fmaf(xv, wv, accV[i]);
            }
        }
    }
    float bkf = bk[f], bvf = bv[f];
#pragma unroll
    for (int i = 0; i < 16; ++i) {
        int r = rowbase + rg + i * 4;
        g_kh[(size_t)r * FF + f] = __float2half_rn(accK[i] + bkf);
        g_vh[(size_t)r * FF + f] = __float2half_rn(accV[i] + bvf);
    }
}

// ---------------------------------------------------------------------------
// Kernel 2: per-node Q projection -> fp16 with 1/sqrt(F) folded in.
// HBM-bound on 512 MB Wq.
// ---------------------------------------------------------------------------
__global__ void q_proj(const float* __restrict__ x,
                       const float* __restrict__ Wq,
                       const float* __restrict__ bq) {
    __shared__ float sx[DD];
    const int n = blockIdx.x;
    sx[threadIdx.x] = x[(size_t)n * DD + threadIdx.x];
    __syncthreads();

    const int f = threadIdx.x >> 2;
    const int part = threadIdx.x & 3;

    const float4* w  = (const float4*)(Wq + ((size_t)n * FF + f) * DD + part * 64);
    const float4* xv = (const float4*)(sx + part * 64);

    float a0 = 0.f, a1 = 0.f, a2 = 0.f, a3 = 0.f;
#pragma unroll
    for (int i = 0; i < 16; i += 4) {
        float4 w0 = w[i + 0], w1 = w[i + 1], w2 = w[i + 2], w3 = w[i + 3];
        float4 x0 = xv[i + 0], x1 = xv[i + 1], x2 = xv[i + 2], x3 = xv[i + 3];
        a0 = fmaf(w0.x, x0.x, fmaf(w0.y, x0.y, fmaf(w0.z, x0.z, fmaf(w0.w, x0.w, a0))));
        a1 = fmaf(w1.x, x1.x, fmaf(w1.y, x1.y, fmaf(w1.z, x1.z, fmaf(w1.w, x1.w, a1))));
        a2 = fmaf(w2.x, x2.x, fmaf(w2.y, x2.y, fmaf(w2.z, x2.z, fmaf(w2.w, x2.w, a2))));
        a3 = fmaf(w3.x, x3.x, fmaf(w3.y, x3.y, fmaf(w3.z, x3.z, fmaf(w3.w, x3.w, a3))));
    }
    float a = (a0 + a1) + (a2 + a3);
    a += __shfl_xor_sync(0xffffffffu, a, 1);
    a += __shfl_xor_sync(0xffffffffu, a, 2);
    if (part == 0)
        g_qh[(size_t)n * FF + f] =
            __float2half_rn((a + bq[(size_t)n * FF + f]) * 0.125f);
}

// ---------------------------------------------------------------------------
// Kernel 3: flash attention, fp16 m16n8k16 (fp32 accum).
//   - K/V staged by cp.async (fp16 in global -> no conversion), double-buffered
//   - 128 q rows per block (8 warps) -> staging traffic halved vs 64 rows
//   - P reused register-direct (S C-fragment == PV A-fragment layout)
// grid (64 q-tiles, 4 kv-splits), 256 threads.
// ---------------------------------------------------------------------------
__global__ void __launch_bounds__(256, 2) attn_kernel() {
    // [buf][matrix(K/V)][row][col], 72-half rows: conflict-free LDSM
    __shared__ __half sKV[2][2][64][72];

    const int qt = blockIdx.x;
    const int sp = blockIdx.y;
    const int warp = threadIdx.x >> 5;
    const int lane = threadIdx.x & 31;
    const int g = lane >> 2;      // groupID 0..7
    const int tig = lane & 3;     // threadID-in-group 0..3

    const int qrow = qt * QROWS + warp * 16;

    // Q fragments (fp16, scale pre-folded), persistent in regs.
    uint32_t qa[4][4];
#pragma unroll
    for (int ko = 0; ko < 4; ++ko) {
        int c0 = ko * 16 + 2 * tig;
        qa[ko][0] = *(const uint32_t*)&g_qh[(size_t)(qrow + g)     * FF + c0];
        qa[ko][1] = *(const uint32_t*)&g_qh[(size_t)(qrow + g + 8) * FF + c0];
        qa[ko][2] = *(const uint32_t*)&g_qh[(size_t)(qrow + g)     * FF + c0 + 8];
        qa[ko][3] = *(const uint32_t*)&g_qh[(size_t)(qrow + g + 8) * FF + c0 + 8];
    }

    float o[8][4];
#pragma unroll
    for (int n = 0; n < 8; ++n)
#pragma unroll
        for (int r = 0; r < 4; ++r) o[n][r] = 0.f;
    float rs0 = 0.f, rs1 = 0.f;

    const uint32_t smem0 = (uint32_t)__cvta_generic_to_shared(&sKV[0][0][0][0]);
    // byte strides
    const uint32_t BUFB = 2 * 64 * 72 * 2;  // 18432
    const uint32_t MATB = 64 * 72 * 2;      // 9216

    // lane-constant LDSM addressing pieces
    const int blk = lane >> 3, r8 = lane & 7;
    const int s_row_off = ((blk >> 1) << 3) + r8;   // S: row = n*8 + this
    const int s_col_off = (blk & 1) << 3;           // S: col = kb + this
    const int v_row_off = ((blk & 1) << 3) + r8;    // V: row = kb + this
    const int v_col_off = (blk >> 1) << 3;          // V: col = n*8 + this

    const int kbase = sp * KEYS_PER_SPLIT;

    // staging lambda replacement (macro-ish): thread copies 4 x 16B per tile
    const int t = threadIdx.x;

    // prologue: stage tile 0 into buf 0
    {
        const int krow = kbase;
#pragma unroll
        for (int p = 0; p < 4; ++p) {
            int idx = t + p * 256;            // 0..1023
            int m = idx >> 9;                 // 0=K, 1=V
            int rem = idx & 511;
            int r = rem >> 3, ch = rem & 7;
            const __half* src = (m ? g_vh : g_kh) + (size_t)(krow + r) * FF + ch * 8;
            cp16(smem0 + m * MATB + (uint32_t)(r * 144 + ch * 16), src);
        }
        cp_commit();
    }

    int buf = 0;
    for (int kt = 0; kt < TILES_PER_SPLIT; ++kt) {
        cp_wait0();
        __syncthreads();   // staged tile visible; prev compute done on other buf

        if (kt + 1 < TILES_PER_SPLIT) {
            const int krow = kbase + (kt + 1) * BK;
            const uint32_t dstb = smem0 + (buf ^ 1) * BUFB;
#pragma unroll
            for (int p = 0; p < 4; ++p) {
                int idx = t + p * 256;
                int m = idx >> 9;
                int rem = idx & 511;
                int r = rem >> 3, ch = rem & 7;
                const __half* src = (m ? g_vh : g_kh) + (size_t)(krow + r) * FF + ch * 8;
                cp16(dstb + m * MATB + (uint32_t)(r * 144 + ch * 16), src);
            }
            cp_commit();
        }

        const uint32_t sK_u = smem0 + buf * BUFB;
        const uint32_t sV_u = sK_u + MATB;

        // S = Q @ K^T : 16 x 64 per warp
        float s[8][4];
#pragma unroll
        for (int n = 0; n < 8; ++n)
#pragma unroll
            for (int r = 0; r < 4; ++r) s[n][r] = 0.f;

#pragma unroll
        for (int ko = 0; ko < 4; ++ko) {
            const int kb = ko << 4;
#pragma unroll
            for (int n2 = 0; n2 < 4; ++n2) {
                const int n = n2 << 1;
                uint32_t a = sK_u +
                    (uint32_t)(((n << 3) + s_row_off) * 144 + (kb + s_col_off) * 2);
                uint32_t b0, b1, b2, b3;
                ldsm_x4(b0, b1, b2, b3, a);
                mma_f16(s[n],     qa[ko], b0, b1);
                mma_f16(s[n + 1], qa[ko], b2, b3);
            }
        }

        // P = exp(S) register-direct into A fragments; O += P @ V
#pragma unroll
        for (int ko = 0; ko < 4; ++ko) {
            const int kb = ko << 4;
            float p00 = fexp(s[2 * ko][0]),     p01 = fexp(s[2 * ko][1]);
            float p10 = fexp(s[2 * ko][2]),     p11 = fexp(s[2 * ko][3]);
            float q00 = fexp(s[2 * ko + 1][0]), q01 = fexp(s[2 * ko + 1][1]);
            float q10 = fexp(s[2 * ko + 1][2]), q11 = fexp(s[2 * ko + 1][3]);
            rs0 += (p00 + p01) + (q00 + q01);
            rs1 += (p10 + p11) + (q10 + q11);
            uint32_t pa[4];
            pa[0] = packh2(p00, p01);
            pa[1] = packh2(p10, p11);
            pa[2] = packh2(q00, q01);
            pa[3] = packh2(q10, q11);
#pragma unroll
            for (int n2 = 0; n2 < 4; ++n2) {
                const int n = n2 << 1;
                uint32_t a = sV_u +
                    (uint32_t)((kb + v_row_off) * 144 + ((n << 3) + v_col_off) * 2);
                uint32_t b0, b1, b2, b3;
                ldsm_x4_t(b0, b1, b2, b3, a);
                mma_f16(o[n],     pa, b0, b1);
                mma_f16(o[n + 1], pa, b2, b3);
            }
        }
        buf ^= 1;
    }

    // reduce row sums across the 4 lanes of each quad (same g)
    rs0 += __shfl_xor_sync(0xffffffffu, rs0, 1);
    rs0 += __shfl_xor_sync(0xffffffffu, rs0, 2);
    rs1 += __shfl_xor_sync(0xffffffffu, rs1, 1);
    rs1 += __shfl_xor_sync(0xffffffffu, rs1, 2);

    float* op = g_op + ((size_t)sp * NN + qrow) * FF;
#pragma unroll
    for (int n = 0; n < 8; ++n) {
        int col = n * 8 + 2 * tig;
        *(float2*)&op[(size_t)g * FF + col]       = make_float2(o[n][0], o[n][1]);
        *(float2*)&op[(size_t)(g + 8) * FF + col] = make_float2(o[n][2], o[n][3]);
    }
    if (tig == 0) {
        g_rs[(size_t)sp * NN + qrow + g]     = rs0;
        g_rs[(size_t)sp * NN + qrow + g + 8] = rs1;
    }
}

// ---------------------------------------------------------------------------
// Kernel 4: merge split-KV partials:  out = sum_s O_s / sum_s rs_s
// ---------------------------------------------------------------------------
__global__ void combine_kernel(float* __restrict__ out) {
    int idx = blockIdx.x * 256 + threadIdx.x;   // 0 .. NN*FF-1
    int i = idx >> 6;
    float num = g_op[idx] + g_op[idx + NF] + g_op[idx + 2 * NF] + g_op[idx + 3 * NF];
    float den = g_rs[i] + g_rs[i + NN] + g_rs[i + 2 * NN] + g_rs[i + 3 * NN];
    out[idx] = num / den;
}

// ---------------------------------------------------------------------------
extern "C" void kernel_launch(void* const* d_in, const int* in_sizes, int n_in,
                              void* d_out, int out_size) {
    const float* x  = (const float*)d_in[0];
    const float* Wk = (const float*)d_in[1];
    const float* bk = (const float*)d_in[2];
    const float* Wv = (const float*)d_in[3];
    const float* bv = (const float*)d_in[4];
    const float* Wq = (const float*)d_in[5];
    const float* bq = (const float*)d_in[6];
    float* out = (float*)d_out;

    kv_proj<<<NN / 64, 256>>>(x, Wk, bk, Wv, bv);
    q_proj<<<NN, 256>>>(x, Wq, bq);
    attn_kernel<<<dim3(NN / QROWS, SPLITS), 256>>>();
    combine_kernel<<<(NN * FF) / 256, 256>>>(out);
}